// round 11
// baseline (speedup 1.0000x reference)
#include <cuda_runtime.h>
#include <cuda_bf16.h>
#include <stdint.h>

// PositionEncoding: out[pos][64] = is_class ? E_class[cid[pos]] : sincos(values[pos])
// sincos dim 2i = sin(2^i*pi*v), 2i+1 = cos(2^i*pi*v); fp32 angle is exactly
// 2^i * fl(v*pi_f) -> 64-bit fixed-point reduction (Q = floor(2^64/2pi)).
//
// R11: wave-quantization fix. Grid 2048 -> 1024 blocks (single wave on 148
// SMs) with 2 positions per thread; both scalar loads + reductions hoisted
// up front, then two shfl-redistributed store loops (R10 structure).

#define NPOS   (64 * 8192)        // 524288 positions
#define BLOCKS 1024               // single wave; each block does 2 tiles of 256

struct PosData { uint32_t uh, ul, pk; };

__device__ __forceinline__ PosData load_reduce(const float* __restrict__ values,
                                               const int*   __restrict__ cid,
                                               const int*   __restrict__ isc,
                                               int pos)
{
    const int   iv = __ldg(&isc[pos]);
    const float v  = __ldg(&values[pos]);
    const int   cv = __ldg(&cid[pos]);

    // theta = fl(v * pi_f), pi_f = 0x40490FDB
    const float th = v * __uint_as_float(0x40490FDBu);
    const uint32_t b  = __float_as_uint(th);          // th >= 0
    const uint32_t ex = b >> 23;                      // biased exponent (<=128)
    const uint32_t m  = (b & 0x7FFFFFu) | (ex ? 0x800000u : 0u);
    const uint64_t p1 = (uint64_t)m * 0x9391054AULL;  // m*Q_lo  (< 2^56)
    const uint64_t p2 = (uint64_t)m * 0x28BE60DBULL;  // m*Q_hi  (< 2^54)
    const uint64_t U0 = (p2 << 10) + (p1 >> 22);      // (m*Q) >> 22
    const uint32_t sh = 128u - ex;
    const uint64_t u  = (sh < 64u) ? (U0 >> sh) : 0ULL;  // frac(th/2pi)*2^64

    PosData d;
    d.ul = (uint32_t)u;
    d.uh = (uint32_t)(u >> 32);
    d.pk = (uint32_t)cv | (iv ? 0x80000000u : 0u);    // cid | class flag
    return d;
}

__device__ __forceinline__ void store_tile(const float4* __restrict__ E,
                                           float4*       __restrict__ out,
                                           int basePos, PosData d,
                                           int chunk, int lvl, int half)
{
    #pragma unroll 4
    for (int k = 0; k < 16; k++) {
        const int j = 2 * k + half;        // source lane / local position

        const uint32_t uh = __shfl_sync(0xFFFFFFFFu, d.uh, j);
        const uint32_t ul = __shfl_sync(0xFFFFFFFFu, d.ul, j);
        const uint32_t pj = __shfl_sync(0xFFFFFFFFu, d.pk, j);

        // frac(2^lvl * u): high word of (u << lvl), signed -> [-pi, pi)
        const int32_t ti  = (int32_t)__funnelshift_l(ul, uh, lvl);
        const float   ang = (float)ti * 1.4629180792671596e-9f;   // *2pi/2^32
        const float s0 = __sinf(ang);
        const float c0 = __cosf(ang);
        const float t2 = c0 + c0;
        const float c1 = fmaf(t2, c0, -1.0f);   // cos(2a)
        const float s1 = t2 * s0;               // sin(2a)

        float4 r = make_float4(s0, c0, s1, c1);
        if (pj & 0x80000000u)                   // class position: gather row
            r = __ldg(&E[(size_t)(pj & 0x7FFFFFFFu) * 16 + chunk]);

        out[(size_t)(basePos + j) * 16 + chunk] = r;
    }
}

__global__ __launch_bounds__(256)
void pe_kernel(const float*  __restrict__ values,
               const float4* __restrict__ E,        // [4096][16] float4
               const int*    __restrict__ cid,
               const int*    __restrict__ isc,
               float4*       __restrict__ out)      // [NPOS][16] float4
{
    const int lane  = threadIdx.x & 31;
    const int wid   = threadIdx.x >> 5;
    const int chunk = lane & 15;
    const int lvl   = chunk << 1;          // 0,2,...,30
    const int half  = lane >> 4;           // 0 or 1

    // two tiles per block: blockIdx.x and blockIdx.x + BLOCKS
    const int base0 = (blockIdx.x          * 8 + wid) * 32;
    const int base1 = ((blockIdx.x + BLOCKS) * 8 + wid) * 32;

    // ---- hoist both tiles' scalar loads + reductions (MLP ~6, ILP 2) ----
    PosData d0 = load_reduce(values, cid, isc, base0 + lane);
    PosData d1 = load_reduce(values, cid, isc, base1 + lane);

    // ---- two shfl-redistributed store loops ----
    store_tile(E, out, base0, d0, chunk, lvl, half);
    store_tile(E, out, base1, d1, chunk, lvl, half);
}

extern "C" void kernel_launch(void* const* d_in, const int* in_sizes, int n_in,
                              void* d_out, int out_size)
{
    const float*  values = (const float*)d_in[0];
    const float4* E      = (const float4*)d_in[1];
    const int*    cids   = (const int*)d_in[2];
    const int*    isc    = (const int*)d_in[3];
    float4*       out    = (float4*)d_out;

    pe_kernel<<<BLOCKS, 256>>>(values, E, cids, isc, out);
}

// round 12
// speedup vs baseline: 1.0106x; 1.0106x over previous
#include <cuda_runtime.h>
#include <cuda_bf16.h>
#include <stdint.h>

// PositionEncoding: out[pos][64] = is_class ? E_class[cid[pos]] : sincos(values[pos])
// sincos dim 2i = sin(2^i*pi*v), 2i+1 = cos(2^i*pi*v); fp32 angle is exactly
// 2^i * fl(v*pi_f) -> 64-bit fixed-point reduction (Q = floor(2^64/2pi)).
//
// R12: split the R10 store loop into two passes.
//  Pass A: class rows only -- pure LDG.128->STG.128 copy, unrolled 8 (MLP 8),
//          predicate from one upfront ballot (no per-iter pk shuffle).
//  Pass B: sincos math + store predicated on !class -- no load dependencies.
// Each output row is written exactly once; store traffic unchanged.

#define NPOS (64 * 8192)                 // 524288 positions

__global__ __launch_bounds__(256)
void pe_kernel(const float*  __restrict__ values,
               const float4* __restrict__ E,        // [4096][16] float4
               const int*    __restrict__ cid,
               const int*    __restrict__ isc,
               float4*       __restrict__ out)      // [NPOS][16] float4
{
    const int tid     = blockIdx.x * blockDim.x + threadIdx.x;
    const int lane    = threadIdx.x & 31;
    const int basePos = (tid >> 5) << 5;    // this warp's 32 positions
    const int myPos   = basePos + lane;

    // ---- coalesced per-position scalar loads (one lane = one position) ----
    const int   iv = __ldg(&isc[myPos]);
    const float v  = __ldg(&values[myPos]);
    const int   cv = __ldg(&cid[myPos]);

    // ---- fixed-point reduction, once per position ----
    const float th = v * __uint_as_float(0x40490FDBu);   // fl(v * pi_f)
    const uint32_t b  = __float_as_uint(th);             // th >= 0
    const uint32_t ex = b >> 23;                         // biased exp (<=128)
    const uint32_t m  = (b & 0x7FFFFFu) | (ex ? 0x800000u : 0u);
    const uint64_t p1 = (uint64_t)m * 0x9391054AULL;     // m*Q_lo
    const uint64_t p2 = (uint64_t)m * 0x28BE60DBULL;     // m*Q_hi
    const uint64_t U0 = (p2 << 10) + (p1 >> 22);         // (m*Q) >> 22
    const uint32_t sh = 128u - ex;
    const uint64_t u  = (sh < 64u) ? (U0 >> sh) : 0ULL;  // frac(th/2pi)*2^64

    const uint32_t u_lo = (uint32_t)u;
    const uint32_t u_hi = (uint32_t)(u >> 32);

    // warp-wide class mask: bit j = (position basePos+j is class)
    const uint32_t clsMask = __ballot_sync(0xFFFFFFFFu, iv != 0);

    const int chunk = lane & 15;
    const int lvl   = chunk << 1;          // 0,2,...,30
    const int half  = lane >> 4;           // 0 or 1

    // ---- Pass A: class rows -- deep-pipelined gather copy ----
    #pragma unroll 8
    for (int k = 0; k < 16; k++) {
        const int j = 2 * k + half;        // local position this half covers
        const uint32_t cj = __shfl_sync(0xFFFFFFFFu, (uint32_t)cv, j);
        if ((clsMask >> j) & 1u) {
            const float4 r = __ldg(&E[(size_t)cj * 16 + chunk]);
            out[(size_t)(basePos + j) * 16 + chunk] = r;
        }
    }

    // ---- Pass B: sincos rows -- pure math, fire-and-forget stores ----
    #pragma unroll 4
    for (int k = 0; k < 16; k++) {
        const int j = 2 * k + half;
        const uint32_t uh = __shfl_sync(0xFFFFFFFFu, u_hi, j);
        const uint32_t ul = __shfl_sync(0xFFFFFFFFu, u_lo, j);
        if (!((clsMask >> j) & 1u)) {
            // frac(2^lvl * u): high word of (u << lvl), signed -> [-pi, pi)
            const int32_t ti  = (int32_t)__funnelshift_l(ul, uh, lvl);
            const float   ang = (float)ti * 1.4629180792671596e-9f;  // *2pi/2^32
            const float s0 = __sinf(ang);
            const float c0 = __cosf(ang);
            const float t2 = c0 + c0;
            const float c1 = fmaf(t2, c0, -1.0f);   // cos(2a)
            const float s1 = t2 * s0;               // sin(2a)
            out[(size_t)(basePos + j) * 16 + chunk] = make_float4(s0, c0, s1, c1);
        }
    }
}

extern "C" void kernel_launch(void* const* d_in, const int* in_sizes, int n_in,
                              void* d_out, int out_size)
{
    const float*  values = (const float*)d_in[0];
    const float4* E      = (const float4*)d_in[1];
    const int*    cids   = (const int*)d_in[2];
    const int*    isc    = (const int*)d_in[3];
    float4*       out    = (float4*)d_out;

    const int threads = 256;
    const int blocks  = NPOS / threads;    // 2048 blocks; 1 thread per position
    pe_kernel<<<blocks, threads>>>(values, E, cids, isc, out);
}

// round 14
// speedup vs baseline: 1.0264x; 1.0156x over previous
#include <cuda_runtime.h>
#include <cuda_bf16.h>
#include <stdint.h>

// PositionEncoding: out[pos][64] = is_class ? E_class[cid[pos]] : sincos(values[pos])
// sincos dim 2i = sin(2^i*pi*v), 2i+1 = cos(2^i*pi*v); fp32 angle is exactly
// 2^i * fl(v*pi_f) -> 64-bit fixed-point reduction (Q = floor(2^64/2pi)).
//
// R13/R14 = R12 + streaming stores (__stcs): the 128MB write-once output no
// longer occupies L2, keeping the 4MB E_class table + inputs L2-resident so
// pass-A gathers hit L2 instead of DRAM.
//  Pass A: class rows -- pipelined LDG.128 -> STG.128.CS copy (MLP 8).
//  Pass B: sincos rows -- pure math, fire-and-forget STG.128.CS.

#define NPOS (64 * 8192)                 // 524288 positions

__global__ __launch_bounds__(256)
void pe_kernel(const float*  __restrict__ values,
               const float4* __restrict__ E,        // [4096][16] float4
               const int*    __restrict__ cid,
               const int*    __restrict__ isc,
               float4*       __restrict__ out)      // [NPOS][16] float4
{
    const int tid     = blockIdx.x * blockDim.x + threadIdx.x;
    const int lane    = threadIdx.x & 31;
    const int basePos = (tid >> 5) << 5;    // this warp's 32 positions
    const int myPos   = basePos + lane;

    // ---- coalesced per-position scalar loads (one lane = one position) ----
    const int   iv = __ldg(&isc[myPos]);
    const float v  = __ldg(&values[myPos]);
    const int   cv = __ldg(&cid[myPos]);

    // ---- fixed-point reduction, once per position ----
    const float th = v * __uint_as_float(0x40490FDBu);   // fl(v * pi_f)
    const uint32_t b  = __float_as_uint(th);             // th >= 0
    const uint32_t ex = b >> 23;                         // biased exp (<=128)
    const uint32_t m  = (b & 0x7FFFFFu) | (ex ? 0x800000u : 0u);
    const uint64_t p1 = (uint64_t)m * 0x9391054AULL;     // m*Q_lo
    const uint64_t p2 = (uint64_t)m * 0x28BE60DBULL;     // m*Q_hi
    const uint64_t U0 = (p2 << 10) + (p1 >> 22);         // (m*Q) >> 22
    const uint32_t sh = 128u - ex;
    const uint64_t u  = (sh < 64u) ? (U0 >> sh) : 0ULL;  // frac(th/2pi)*2^64

    const uint32_t u_lo = (uint32_t)u;
    const uint32_t u_hi = (uint32_t)(u >> 32);

    // warp-wide class mask: bit j = (position basePos+j is class)
    const uint32_t clsMask = __ballot_sync(0xFFFFFFFFu, iv != 0);

    const int chunk = lane & 15;
    const int lvl   = chunk << 1;          // 0,2,...,30
    const int half  = lane >> 4;           // 0 or 1

    // ---- Pass A: class rows -- deep-pipelined gather copy ----
    #pragma unroll 8
    for (int k = 0; k < 16; k++) {
        const int j = 2 * k + half;        // local position this half covers
        const uint32_t cj = __shfl_sync(0xFFFFFFFFu, (uint32_t)cv, j);
        if ((clsMask >> j) & 1u) {
            const float4 r = __ldg(&E[(size_t)cj * 16 + chunk]);
            __stcs(&out[(size_t)(basePos + j) * 16 + chunk], r);
        }
    }

    // ---- Pass B: sincos rows -- pure math, fire-and-forget stores ----
    #pragma unroll 4
    for (int k = 0; k < 16; k++) {
        const int j = 2 * k + half;
        const uint32_t uh = __shfl_sync(0xFFFFFFFFu, u_hi, j);
        const uint32_t ul = __shfl_sync(0xFFFFFFFFu, u_lo, j);
        if (!((clsMask >> j) & 1u)) {
            // frac(2^lvl * u): high word of (u << lvl), signed -> [-pi, pi)
            const int32_t ti  = (int32_t)__funnelshift_l(ul, uh, lvl);
            const float   ang = (float)ti * 1.4629180792671596e-9f;  // *2pi/2^32
            const float s0 = __sinf(ang);
            const float c0 = __cosf(ang);
            const float t2 = c0 + c0;
            const float c1 = fmaf(t2, c0, -1.0f);   // cos(2a)
            const float s1 = t2 * s0;               // sin(2a)
            __stcs(&out[(size_t)(basePos + j) * 16 + chunk],
                   make_float4(s0, c0, s1, c1));
        }
    }
}

extern "C" void kernel_launch(void* const* d_in, const int* in_sizes, int n_in,
                              void* d_out, int out_size)
{
    const float*  values = (const float*)d_in[0];
    const float4* E      = (const float4*)d_in[1];
    const int*    cids   = (const int*)d_in[2];
    const int*    isc    = (const int*)d_in[3];
    float4*       out    = (float4*)d_out;

    const int threads = 256;
    const int blocks  = NPOS / threads;    // 2048 blocks; 1 thread per position
    pe_kernel<<<blocks, threads>>>(values, E, cids, isc, out);
}

// round 15
// speedup vs baseline: 1.0822x; 1.0544x over previous
#include <cuda_runtime.h>
#include <cuda_bf16.h>
#include <stdint.h>

// PositionEncoding: out[pos][64] = is_class ? E_class[cid[pos]] : sincos(values[pos])
// sincos dim 2i = sin(2^i*pi*v), 2i+1 = cos(2^i*pi*v); fp32 angle is exactly
// 2^i * fl(v*pi_f) -> 64-bit fixed-point reduction (Q = floor(2^64/2pi)).
//
// R15 instruction diet:
//  Pass A (class rows): fully-unrolled predicated gather copy (MLP high),
//    pre-offset pointers so stores use immediate offsets.
//  Pass B (sincos rows): COMPACTED bit-loop over the sincos mask, two
//    positions per iteration (half 0 = first set bit, half 1 = second).
//    Warp stays fully converged (mask is warp-uniform) -> shfl_sync legal.
//    Skips the ~50% predicated-off iterations entirely.

#define NPOS (64 * 8192)                 // 524288 positions

__global__ __launch_bounds__(256)
void pe_kernel(const float*  __restrict__ values,
               const float4* __restrict__ E,        // [4096][16] float4
               const int*    __restrict__ cid,
               const int*    __restrict__ isc,
               float4*       __restrict__ out)      // [NPOS][16] float4
{
    const int tid     = blockIdx.x * blockDim.x + threadIdx.x;
    const int lane    = threadIdx.x & 31;
    const int basePos = (tid >> 5) << 5;    // this warp's 32 positions
    const int myPos   = basePos + lane;

    // ---- coalesced per-position scalar loads (one lane = one position) ----
    const int   iv = __ldg(&isc[myPos]);
    const float v  = __ldg(&values[myPos]);
    const int   cv = __ldg(&cid[myPos]);

    // ---- fixed-point reduction, once per position ----
    const float th = v * __uint_as_float(0x40490FDBu);   // fl(v * pi_f)
    const uint32_t b  = __float_as_uint(th);             // th >= 0
    const uint32_t ex = b >> 23;                         // biased exp (<=128)
    const uint32_t m  = (b & 0x7FFFFFu) | (ex ? 0x800000u : 0u);
    const uint64_t p1 = (uint64_t)m * 0x9391054AULL;     // m*Q_lo
    const uint64_t p2 = (uint64_t)m * 0x28BE60DBULL;     // m*Q_hi
    const uint64_t U0 = (p2 << 10) + (p1 >> 22);         // (m*Q) >> 22
    const uint32_t sh = 128u - ex;
    const uint64_t u  = (sh < 64u) ? (U0 >> sh) : 0ULL;  // frac(th/2pi)*2^64

    const uint32_t u_lo = (uint32_t)u;
    const uint32_t u_hi = (uint32_t)(u >> 32);

    // warp-wide class mask: bit j = (position basePos+j is class)
    const uint32_t clsMask = __ballot_sync(0xFFFFFFFFu, iv != 0);

    const int chunk = lane & 15;
    const int lvl   = chunk << 1;          // 0,2,...,30
    const int half  = lane >> 4;           // 0 or 1

    // pre-offset pointers: per-iteration addresses become immediate offsets
    float4*       outw = out + (size_t)basePos * 16 + chunk;   // outw[j*16]
    const float4* Ec   = E + chunk;                            // Ec[cj*16]

    // ---- Pass A: class rows -- fully-unrolled predicated gather copy ----
    #pragma unroll 16
    for (int k = 0; k < 16; k++) {
        const int j = 2 * k + half;        // local position this half covers
        const uint32_t cj = __shfl_sync(0xFFFFFFFFu, (uint32_t)cv, j);
        if ((clsMask >> j) & 1u) {
            const float4 r = __ldg(&Ec[(size_t)cj * 16]);
            __stcs(&outw[j * 16], r);
        }
    }

    // ---- Pass B: sincos rows -- compacted bit-loop, 2 positions/iter ----
    uint32_t ms = ~clsMask;                // sincos positions (all 32 bits valid)
    while (ms) {
        const int j0 = __ffs(ms) - 1;  ms &= ms - 1;
        int j1 = -1;
        if (ms) { j1 = __ffs(ms) - 1;  ms &= ms - 1; }

        const int  j   = half ? j1 : j0;   // half 1 idles if odd count
        const int  js  = (j < 0) ? 0 : j;  // safe shfl source
        const uint32_t uh = __shfl_sync(0xFFFFFFFFu, u_hi, js);
        const uint32_t ul = __shfl_sync(0xFFFFFFFFu, u_lo, js);

        if (j >= 0) {
            // frac(2^lvl * u): high word of (u << lvl), signed -> [-pi, pi)
            const int32_t ti  = (int32_t)__funnelshift_l(ul, uh, lvl);
            const float   ang = (float)ti * 1.4629180792671596e-9f;  // *2pi/2^32
            const float s0 = __sinf(ang);
            const float c0 = __cosf(ang);
            const float t2 = c0 + c0;
            const float c1 = fmaf(t2, c0, -1.0f);   // cos(2a)
            const float s1 = t2 * s0;               // sin(2a)
            __stcs(&outw[j * 16], make_float4(s0, c0, s1, c1));
        }
    }
}

extern "C" void kernel_launch(void* const* d_in, const int* in_sizes, int n_in,
                              void* d_out, int out_size)
{
    const float*  values = (const float*)d_in[0];
    const float4* E      = (const float4*)d_in[1];
    const int*    cids   = (const int*)d_in[2];
    const int*    isc    = (const int*)d_in[3];
    float4*       out    = (float4*)d_out;

    const int threads = 256;
    const int blocks  = NPOS / threads;    // 2048 blocks; 1 thread per position
    pe_kernel<<<blocks, threads>>>(values, E, cids, isc, out);
}